// round 1
// baseline (speedup 1.0000x reference)
#include <cuda_runtime.h>
#include <math_constants.h>

// Problem constants
#define BB 4
#define TT 2048
#define CC 1024
#define HH 1024

// Scratch (static device globals; no runtime allocation)
__device__ float g_Q[(size_t)BB * TT * HH];
__device__ float g_K[(size_t)BB * TT * HH];
__device__ float g_V[(size_t)BB * TT * HH];
__device__ float g_S[(size_t)BB * TT * TT];

// ---------------------------------------------------------------------------
// GEMM NN: C[M,N] = A[M,K] @ W[K,N], M=8192, N=1024, K=1024
// 128x128 block tile, BK=16, 256 threads, 8x8 per-thread microtile.
// ---------------------------------------------------------------------------
__global__ void __launch_bounds__(256) gemm_qkv(
    const float* __restrict__ A, const float* __restrict__ W,
    float* __restrict__ C)
{
    const int N = HH, K = CC;
    __shared__ float As[16][132];   // [k][m], padded
    __shared__ float Bs[16][128];   // [k][n]

    const int t  = threadIdx.x;
    const int tx = t & 15;          // N direction
    const int ty = t >> 4;          // M direction
    const int m0 = blockIdx.y * 128;
    const int n0 = blockIdx.x * 128;

    float acc[8][8] = {};

    for (int k0 = 0; k0 < K; k0 += 16) {
        // Load A tile 128x16, store transposed into As[k][m]
        #pragma unroll
        for (int i = 0; i < 2; i++) {
            int p   = t + i * 256;       // 0..511 float4 slots
            int row = p >> 2;            // 4 float4 per row
            int c4  = p & 3;
            float4 v = *(const float4*)&A[(size_t)(m0 + row) * K + k0 + c4 * 4];
            As[c4 * 4 + 0][row] = v.x;
            As[c4 * 4 + 1][row] = v.y;
            As[c4 * 4 + 2][row] = v.z;
            As[c4 * 4 + 3][row] = v.w;
        }
        // Load B tile 16x128 directly
        #pragma unroll
        for (int i = 0; i < 2; i++) {
            int p   = t + i * 256;
            int row = p >> 5;            // 32 float4 per row
            int c4  = p & 31;
            float4 v = *(const float4*)&W[(size_t)(k0 + row) * N + n0 + c4 * 4];
            *(float4*)&Bs[row][c4 * 4] = v;
        }
        __syncthreads();

        #pragma unroll
        for (int k = 0; k < 16; k++) {
            float ra[8], rb[8];
            #pragma unroll
            for (int i = 0; i < 8; i++) ra[i] = As[k][ty * 8 + i];
            #pragma unroll
            for (int j = 0; j < 8; j++) rb[j] = Bs[k][tx * 8 + j];
            #pragma unroll
            for (int i = 0; i < 8; i++)
                #pragma unroll
                for (int j = 0; j < 8; j++)
                    acc[i][j] += ra[i] * rb[j];
        }
        __syncthreads();
    }

    #pragma unroll
    for (int i = 0; i < 8; i++) {
        #pragma unroll
        for (int j = 0; j < 8; j += 4) {
            float4 v = make_float4(acc[i][j], acc[i][j+1], acc[i][j+2], acc[i][j+3]);
            *(float4*)&C[(size_t)(m0 + ty * 8 + i) * N + n0 + tx * 8 + j] = v;
        }
    }
}

// ---------------------------------------------------------------------------
// Batched GEMM NT with scaling: S_b = (Q_b @ K_b^T) * scale, skip tiles
// fully above the causal diagonal. M=N=T=2048, K=H=1024, blockIdx.z = batch.
// ---------------------------------------------------------------------------
__global__ void __launch_bounds__(256) gemm_qkt(
    const float* __restrict__ Q, const float* __restrict__ Km,
    float* __restrict__ S, float scale)
{
    const int bx = blockIdx.x;   // key tile (cols)
    const int by = blockIdx.y;   // query tile (rows)
    if (bx > by) return;         // whole tile above diagonal — softmax never reads it

    const int b = blockIdx.z;
    const float* Qb = Q  + (size_t)b * TT * HH;
    const float* Kb = Km + (size_t)b * TT * HH;
    float*       Sb = S  + (size_t)b * TT * TT;

    __shared__ float As[16][132];   // [k][m]
    __shared__ float Bs[16][132];   // [k][n]

    const int t  = threadIdx.x;
    const int tx = t & 15;
    const int ty = t >> 4;
    const int m0 = by * 128;
    const int n0 = bx * 128;

    float acc[8][8] = {};

    for (int k0 = 0; k0 < HH; k0 += 16) {
        #pragma unroll
        for (int i = 0; i < 2; i++) {
            int p   = t + i * 256;
            int row = p >> 2;
            int c4  = p & 3;
            float4 va = *(const float4*)&Qb[(size_t)(m0 + row) * HH + k0 + c4 * 4];
            As[c4 * 4 + 0][row] = va.x;
            As[c4 * 4 + 1][row] = va.y;
            As[c4 * 4 + 2][row] = va.z;
            As[c4 * 4 + 3][row] = va.w;
            float4 vb = *(const float4*)&Kb[(size_t)(n0 + row) * HH + k0 + c4 * 4];
            Bs[c4 * 4 + 0][row] = vb.x;
            Bs[c4 * 4 + 1][row] = vb.y;
            Bs[c4 * 4 + 2][row] = vb.z;
            Bs[c4 * 4 + 3][row] = vb.w;
        }
        __syncthreads();

        #pragma unroll
        for (int k = 0; k < 16; k++) {
            float ra[8], rb[8];
            #pragma unroll
            for (int i = 0; i < 8; i++) ra[i] = As[k][ty * 8 + i];
            #pragma unroll
            for (int j = 0; j < 8; j++) rb[j] = Bs[k][tx * 8 + j];
            #pragma unroll
            for (int i = 0; i < 8; i++)
                #pragma unroll
                for (int j = 0; j < 8; j++)
                    acc[i][j] += ra[i] * rb[j];
        }
        __syncthreads();
    }

    #pragma unroll
    for (int i = 0; i < 8; i++) {
        #pragma unroll
        for (int j = 0; j < 8; j += 4) {
            float4 v = make_float4(acc[i][j]   * scale, acc[i][j+1] * scale,
                                   acc[i][j+2] * scale, acc[i][j+3] * scale);
            *(float4*)&Sb[(size_t)(m0 + ty * 8 + i) * TT + n0 + tx * 8 + j] = v;
        }
    }
}

// ---------------------------------------------------------------------------
// Causal softmax in place: row t reads S[t, 0..t], writes probs there and
// zeros for columns > t (so the PV GEMM can read dense tiles).
// One block (256 threads) per row; grid (T, B).
// ---------------------------------------------------------------------------
__global__ void __launch_bounds__(256) softmax_causal(float* __restrict__ S)
{
    const int t = blockIdx.x;
    const int b = blockIdx.y;
    float* row = S + ((size_t)b * TT + t) * TT;
    const int len = t + 1;
    const int tid  = threadIdx.x;
    const int lane = tid & 31;
    const int warp = tid >> 5;

    __shared__ float red[8];

    float v[8];
    float mx = -CUDART_INF_F;
    #pragma unroll
    for (int i = 0; i < 8; i++) {
        int idx = tid + i * 256;
        v[i] = (idx < len) ? row[idx] : -CUDART_INF_F;
        mx = fmaxf(mx, v[i]);
    }
    #pragma unroll
    for (int o = 16; o > 0; o >>= 1)
        mx = fmaxf(mx, __shfl_xor_sync(0xffffffffu, mx, o));
    if (lane == 0) red[warp] = mx;
    __syncthreads();
    float bmx = red[lane & 7];
    #pragma unroll
    for (int o = 4; o > 0; o >>= 1)
        bmx = fmaxf(bmx, __shfl_xor_sync(0xffffffffu, bmx, o));
    bmx = __shfl_sync(0xffffffffu, bmx, 0);

    float sum = 0.f;
    #pragma unroll
    for (int i = 0; i < 8; i++) {
        int idx = tid + i * 256;
        v[i] = (idx < len) ? __expf(v[i] - bmx) : 0.f;
        sum += v[i];
    }
    #pragma unroll
    for (int o = 16; o > 0; o >>= 1)
        sum += __shfl_xor_sync(0xffffffffu, sum, o);
    if (lane == 0) red[warp] = sum;
    __syncthreads();
    float bsum = red[lane & 7];
    #pragma unroll
    for (int o = 4; o > 0; o >>= 1)
        bsum += __shfl_xor_sync(0xffffffffu, bsum, o);
    bsum = __shfl_sync(0xffffffffu, bsum, 0);

    const float inv = 1.0f / bsum;
    #pragma unroll
    for (int i = 0; i < 8; i++) {
        int idx = tid + i * 256;
        row[idx] = v[i] * inv;   // zeros beyond len stay zero
    }
}

// ---------------------------------------------------------------------------
// Batched GEMM NN with causal K-limit: O_b = P_b[T,T] @ V_b[T,H].
// K-loop bounded by (rowTile+1)*128 — everything past it is exact zero.
// ---------------------------------------------------------------------------
__global__ void __launch_bounds__(256) gemm_pv(
    const float* __restrict__ P, const float* __restrict__ V,
    float* __restrict__ O)
{
    const int bx = blockIdx.x;   // H tile
    const int by = blockIdx.y;   // T row tile
    const int b  = blockIdx.z;
    const float* Pb = P + (size_t)b * TT * TT;
    const float* Vb = V + (size_t)b * TT * HH;
    float*       Ob = O + (size_t)b * TT * HH;

    __shared__ float As[16][132];
    __shared__ float Bs[16][128];

    const int t  = threadIdx.x;
    const int tx = t & 15;
    const int ty = t >> 4;
    const int m0 = by * 128;
    const int n0 = bx * 128;
    const int kmax = (by + 1) * 128;   // causal bound

    float acc[8][8] = {};

    for (int k0 = 0; k0 < kmax; k0 += 16) {
        #pragma unroll
        for (int i = 0; i < 2; i++) {
            int p   = t + i * 256;
            int row = p >> 2;
            int c4  = p & 3;
            float4 va = *(const float4*)&Pb[(size_t)(m0 + row) * TT + k0 + c4 * 4];
            As[c4 * 4 + 0][row] = va.x;
            As[c4 * 4 + 1][row] = va.y;
            As[c4 * 4 + 2][row] = va.z;
            As[c4 * 4 + 3][row] = va.w;
        }
        #pragma unroll
        for (int i = 0; i < 2; i++) {
            int p   = t + i * 256;
            int row = p >> 5;
            int c4  = p & 31;
            float4 v = *(const float4*)&Vb[(size_t)(k0 + row) * HH + n0 + c4 * 4];
            *(float4*)&Bs[row][c4 * 4] = v;
        }
        __syncthreads();

        #pragma unroll
        for (int k = 0; k < 16; k++) {
            float ra[8], rb[8];
            #pragma unroll
            for (int i = 0; i < 8; i++) ra[i] = As[k][ty * 8 + i];
            #pragma unroll
            for (int j = 0; j < 8; j++) rb[j] = Bs[k][tx * 8 + j];
            #pragma unroll
            for (int i = 0; i < 8; i++)
                #pragma unroll
                for (int j = 0; j < 8; j++)
                    acc[i][j] += ra[i] * rb[j];
        }
        __syncthreads();
    }

    #pragma unroll
    for (int i = 0; i < 8; i++) {
        #pragma unroll
        for (int j = 0; j < 8; j += 4) {
            float4 v = make_float4(acc[i][j], acc[i][j+1], acc[i][j+2], acc[i][j+3]);
            *(float4*)&Ob[(size_t)(m0 + ty * 8 + i) * HH + n0 + tx * 8 + j] = v;
        }
    }
}

// ---------------------------------------------------------------------------
extern "C" void kernel_launch(void* const* d_in, const int* in_sizes, int n_in,
                              void* d_out, int out_size)
{
    // Identify x (unique size B*T*C); remaining inputs keep order Wk, Wq, Wv.
    int xi = 0;
    for (int i = 0; i < n_in; i++)
        if (in_sizes[i] == BB * TT * CC) { xi = i; break; }
    const float* x = (const float*)d_in[xi];
    const float* w[3];
    int wi = 0;
    for (int i = 0; i < n_in && wi < 3; i++)
        if (i != xi) w[wi++] = (const float*)d_in[i];
    const float* Wk = w[0];
    const float* Wq = w[1];
    const float* Wv = w[2];
    float* out = (float*)d_out;

    float *Q, *K, *V, *S;
    cudaGetSymbolAddress((void**)&Q, g_Q);
    cudaGetSymbolAddress((void**)&K, g_K);
    cudaGetSymbolAddress((void**)&V, g_V);
    cudaGetSymbolAddress((void**)&S, g_S);

    const float scale = 1.0f / 32.0f;   // 1/sqrt(1024)

    dim3 gProj(HH / 128, (BB * TT) / 128);
    gemm_qkv<<<gProj, 256>>>(x, Wk, K);
    gemm_qkv<<<gProj, 256>>>(x, Wq, Q);
    gemm_qkv<<<gProj, 256>>>(x, Wv, V);

    dim3 gS(TT / 128, TT / 128, BB);
    gemm_qkt<<<gS, 256>>>(Q, K, S, scale);

    dim3 gSm(TT, BB);
    softmax_causal<<<gSm, 256>>>(S);

    dim3 gPV(HH / 128, TT / 128, BB);
    gemm_pv<<<gPV, 256>>>(S, V, out);
}

// round 3
// speedup vs baseline: 2.3519x; 2.3519x over previous
#include <cuda_runtime.h>
#include <cuda_bf16.h>
#include <cstdint>
#include <math_constants.h>

#define BB 4
#define TT 2048
#define CC 1024
#define HH 1024

typedef __nv_bfloat16 bf16;

// ---------------- scratch (static device globals; no runtime allocation) ----
__device__ __align__(16) bf16  g_xhi[(size_t)BB*TT*CC];
__device__ __align__(16) bf16  g_xlo[(size_t)BB*TT*CC];
__device__ __align__(16) bf16  g_Wthi[3][(size_t)CC*HH];   // W^T [H][C]
__device__ __align__(16) bf16  g_Wtlo[3][(size_t)CC*HH];
__device__ __align__(16) bf16  g_Qhi[(size_t)BB*TT*HH], g_Qlo[(size_t)BB*TT*HH];
__device__ __align__(16) bf16  g_Khi[(size_t)BB*TT*HH], g_Klo[(size_t)BB*TT*HH];
__device__ __align__(16) float g_Vf [(size_t)BB*TT*HH];
__device__ __align__(16) bf16  g_Vthi[(size_t)BB*HH*TT], g_Vtlo[(size_t)BB*HH*TT];
__device__ __align__(16) float g_S  [(size_t)BB*TT*TT];
__device__ __align__(16) bf16  g_Phi[(size_t)BB*TT*TT], g_Plo[(size_t)BB*TT*TT];

// ---------------- PTX helpers ----------------------------------------------
__device__ __forceinline__ uint32_t smem_u32(const void* p) {
    uint32_t a;
    asm("{ .reg .u64 t; cvta.to.shared.u64 t, %1; cvt.u32.u64 %0, t; }"
        : "=r"(a) : "l"(p));
    return a;
}
__device__ __forceinline__ void ldsm4(uint32_t* r, uint32_t addr) {
    asm volatile("ldmatrix.sync.aligned.m8n8.x4.shared.b16 {%0,%1,%2,%3}, [%4];"
                 : "=r"(r[0]), "=r"(r[1]), "=r"(r[2]), "=r"(r[3]) : "r"(addr));
}
__device__ __forceinline__ void mma16816(float* c, const uint32_t* a, const uint32_t* b) {
    asm volatile(
        "mma.sync.aligned.m16n8k16.row.col.f32.bf16.bf16.f32 "
        "{%0,%1,%2,%3}, {%4,%5,%6,%7}, {%8,%9}, {%0,%1,%2,%3};"
        : "+f"(c[0]), "+f"(c[1]), "+f"(c[2]), "+f"(c[3])
        : "r"(a[0]), "r"(a[1]), "r"(a[2]), "r"(a[3]), "r"(b[0]), "r"(b[1]));
}
__device__ __forceinline__ void cpasync16(uint32_t saddr, const void* g) {
    asm volatile("cp.async.cg.shared.global [%0], [%1], 16;" :: "r"(saddr), "l"(g));
}
#define CP_COMMIT()  asm volatile("cp.async.commit_group;" ::: "memory")
#define CP_WAIT1()   asm volatile("cp.async.wait_group 1;" ::: "memory")

// ---------------- bf16x3 tensor-core GEMM ----------------------------------
// D[m,n] = sum_k A[m,k]*B[n,k]; A,B K-major (row stride = K elements).
// 128x128 tile, BK=32, 3-stage cp.async pipeline, 256 threads.
// CAUSAL: 0 none, 1 skip tiles bx>by (QK^T), 2 k-limit (by+1)*128 (PV)
#define TILE_B   10240          // 128 rows * 80 bytes (32 bf16 + 8 pad)
#define STAGE_B  40960          // 4 tiles (Ah, Al, Bh, Bl)
#define SMEMSZ   122880         // 3 stages

template<int CAUSAL>
__global__ void __launch_bounds__(256) mma_gemm(
    const bf16* __restrict__ Ah, const bf16* __restrict__ Al, size_t aB,
    const bf16* __restrict__ Bh, const bf16* __restrict__ Bl, size_t bB,
    int K, float* __restrict__ Cf, bf16* __restrict__ Chi, bf16* __restrict__ Clo,
    size_t cB, int ldc, float scale)
{
    extern __shared__ char smem[];
    const int bx = blockIdx.x, by = blockIdx.y, bz = blockIdx.z;
    if (CAUSAL == 1 && bx > by) return;
    int kmax = K;
    if (CAUSAL == 2) { int kl = (by + 1) * 128; kmax = kl < K ? kl : K; }
    const int NC = kmax / 32;

    const int tid  = threadIdx.x;
    const int lane = tid & 31;
    const int warp = tid >> 5;
    const int wm   = warp & 1;     // 2 warps in M -> 64 rows each
    const int wn   = warp >> 1;    // 4 warps in N -> 32 cols each
    const uint32_t sb = smem_u32(smem);

    const bf16* srcs[4];
    srcs[0] = Ah + bz * aB + (size_t)by * 128 * K;
    srcs[1] = Al + bz * aB + (size_t)by * 128 * K;
    srcs[2] = Bh + bz * bB + (size_t)bx * 128 * K;
    srcs[3] = Bl + bz * bB + (size_t)bx * 128 * K;

    auto issue = [&](int c) {
        const int k0 = c * 32;
        const uint32_t base = sb + (c % 3) * STAGE_B;
        #pragma unroll
        for (int t4 = 0; t4 < 4; t4++) {
            const bf16* src = srcs[t4] + k0;
            const uint32_t tb = base + t4 * TILE_B;
            #pragma unroll
            for (int i = 0; i < 2; i++) {
                int p   = tid + i * 256;
                int row = p >> 2, cc = p & 3;
                cpasync16(tb + row * 80 + cc * 16, src + (size_t)row * K + cc * 8);
            }
        }
    };

    float acc[4][4][4] = {};

    issue(0); CP_COMMIT();
    issue(1); CP_COMMIT();

    for (int c = 0; c < NC; c++) {
        CP_WAIT1();
        __syncthreads();
        if (c + 2 < NC) issue(c + 2);
        CP_COMMIT();

        const uint32_t base = sb + (c % 3) * STAGE_B;
        const uint32_t tAh = base, tAl = base + TILE_B;
        const uint32_t tBh = base + 2 * TILE_B, tBl = base + 3 * TILE_B;

        #pragma unroll
        for (int k16 = 0; k16 < 2; k16++) {
            uint32_t ah[4][4], al[4][4], bh[2][4], bl[2][4];
            const int ar   = lane & 15;
            const int aoff = (k16 * 16 + (lane >> 4) * 8) * 2;
            #pragma unroll
            for (int mt = 0; mt < 4; mt++) {
                const uint32_t row = wm * 64 + mt * 16 + ar;
                ldsm4(ah[mt], tAh + row * 80 + aoff);
                ldsm4(al[mt], tAl + row * 80 + aoff);
            }
            const int br   = (lane & 7) + ((lane >> 4) << 3);
            const int boff = (k16 * 16 + ((lane >> 3) & 1) * 8) * 2;
            #pragma unroll
            for (int np = 0; np < 2; np++) {
                const uint32_t row = wn * 32 + np * 16 + br;
                ldsm4(bh[np], tBh + row * 80 + boff);
                ldsm4(bl[np], tBl + row * 80 + boff);
            }
            #pragma unroll
            for (int mt = 0; mt < 4; mt++)
                #pragma unroll
                for (int nt = 0; nt < 4; nt++) {
                    const uint32_t* bhp = &bh[nt >> 1][(nt & 1) * 2];
                    const uint32_t* blp = &bl[nt >> 1][(nt & 1) * 2];
                    mma16816(acc[mt][nt], ah[mt], bhp);
                    mma16816(acc[mt][nt], ah[mt], blp);
                    mma16816(acc[mt][nt], al[mt], bhp);
                }
        }
    }

    // ---------------- epilogue: registers -> global -------------------------
    const size_t cbase = bz * cB;
    const int m0  = by * 128 + wm * 64;
    const int n0g = bx * 128 + wn * 32;

    #pragma unroll
    for (int mt = 0; mt < 4; mt++)
        #pragma unroll
        for (int nt = 0; nt < 4; nt++) {
            const int r  = m0 + mt * 16 + (lane >> 2);
            const int cc = n0g + nt * 8 + (lane & 3) * 2;
            const float v0 = acc[mt][nt][0], v1 = acc[mt][nt][1];
            const float v2 = acc[mt][nt][2], v3 = acc[mt][nt][3];
            const size_t o0 = cbase + (size_t)r * ldc + cc;
            const size_t o1 = cbase + (size_t)(r + 8) * ldc + cc;
            if (Chi) {
                __nv_bfloat162 h0 = __floats2bfloat162_rn(v0, v1);
                __nv_bfloat162 h1 = __floats2bfloat162_rn(v2, v3);
                *(__nv_bfloat162*)(Chi + o0) = h0;
                *(__nv_bfloat162*)(Chi + o1) = h1;
                *(__nv_bfloat162*)(Clo + o0) = __floats2bfloat162_rn(
                    v0 - __bfloat162float(h0.x), v1 - __bfloat162float(h0.y));
                *(__nv_bfloat162*)(Clo + o1) = __floats2bfloat162_rn(
                    v2 - __bfloat162float(h1.x), v3 - __bfloat162float(h1.y));
            } else {
                *(float2*)(Cf + o0) = make_float2(v0 * scale, v1 * scale);
                *(float2*)(Cf + o1) = make_float2(v2 * scale, v3 * scale);
            }
        }
}

// ---------------- fp32 -> bf16 hi/lo split (elementwise) --------------------
__global__ void __launch_bounds__(256) split_f32(
    const float* __restrict__ in, bf16* __restrict__ hi, bf16* __restrict__ lo, int n4)
{
    int i = blockIdx.x * blockDim.x + threadIdx.x;
    if (i >= n4) return;
    float4 v = ((const float4*)in)[i];
    __nv_bfloat162 h0 = __floats2bfloat162_rn(v.x, v.y);
    __nv_bfloat162 h1 = __floats2bfloat162_rn(v.z, v.w);
    ((__nv_bfloat162*)hi)[2 * i]     = h0;
    ((__nv_bfloat162*)hi)[2 * i + 1] = h1;
    ((__nv_bfloat162*)lo)[2 * i]     = __floats2bfloat162_rn(
        v.x - __bfloat162float(h0.x), v.y - __bfloat162float(h0.y));
    ((__nv_bfloat162*)lo)[2 * i + 1] = __floats2bfloat162_rn(
        v.z - __bfloat162float(h1.x), v.w - __bfloat162float(h1.y));
}

// ---------------- fp32 transpose + bf16 hi/lo split -------------------------
__global__ void transpose_split(const float* __restrict__ in,
                                bf16* __restrict__ ohi, bf16* __restrict__ olo,
                                int rows, int cols)
{
    __shared__ float t[32][33];
    const size_t base = (size_t)blockIdx.z * rows * cols;
    const int c0 = blockIdx.x * 32, r0 = blockIdx.y * 32;
    const int tx = threadIdx.x, ty = threadIdx.y;
    #pragma unroll
    for (int i = 0; i < 4; i++)
        t[ty + 8 * i][tx] = in[base + (size_t)(r0 + ty + 8 * i) * cols + c0 + tx];
    __syncthreads();
    #pragma unroll
    for (int i = 0; i < 4; i++) {
        float v = t[tx][ty + 8 * i];
        size_t o = base + (size_t)(c0 + ty + 8 * i) * rows + r0 + tx;
        bf16 h = __float2bfloat16(v);
        ohi[o] = h;
        olo[o] = __float2bfloat16(v - __bfloat162float(h));
    }
}

// ---------------- causal softmax: fp32 S row -> bf16 hi/lo P ----------------
__global__ void __launch_bounds__(256) softmax_split(
    const float* __restrict__ S, bf16* __restrict__ Phi, bf16* __restrict__ Plo)
{
    const int t = blockIdx.x;
    const int b = blockIdx.y;
    const size_t rbase = ((size_t)b * TT + t) * TT;
    const float* row = S + rbase;
    const int len = t + 1;
    const int tid = threadIdx.x;
    const int lane = tid & 31;
    const int warp = tid >> 5;

    __shared__ float red[8];

    float v[8];
    float mx = -CUDART_INF_F;
    #pragma unroll
    for (int i = 0; i < 8; i++) {
        int idx = tid + i * 256;
        v[i] = (idx < len) ? row[idx] : -CUDART_INF_F;
        mx = fmaxf(mx, v[i]);
    }
    #pragma unroll
    for (int o = 16; o > 0; o >>= 1)
        mx = fmaxf(mx, __shfl_xor_sync(0xffffffffu, mx, o));
    if (lane == 0) red[warp] = mx;
    __syncthreads();
    float bmx = red[lane & 7];
    #pragma unroll
    for (int o = 4; o > 0; o >>= 1)
        bmx = fmaxf(bmx, __shfl_xor_sync(0xffffffffu, bmx, o));
    bmx = __shfl_sync(0xffffffffu, bmx, 0);

    float sum = 0.f;
    #pragma unroll
    for (int i = 0; i < 8; i++) {
        int idx = tid + i * 256;
        v[i] = (idx < len) ? __expf(v[i] - bmx) : 0.f;
        sum += v[i];
    }
    #pragma unroll
    for (int o = 16; o > 0; o >>= 1)
        sum += __shfl_xor_sync(0xffffffffu, sum, o);
    if (lane == 0) red[warp] = sum;
    __syncthreads();
    float bsum = red[lane & 7];
    #pragma unroll
    for (int o = 4; o > 0; o >>= 1)
        bsum += __shfl_xor_sync(0xffffffffu, bsum, o);
    bsum = __shfl_sync(0xffffffffu, bsum, 0);

    const float inv = 1.0f / bsum;
    #pragma unroll
    for (int i = 0; i < 8; i++) {
        int idx = tid + i * 256;
        float p = v[i] * inv;
        bf16 h = __float2bfloat16(p);
        Phi[rbase + idx] = h;
        Plo[rbase + idx] = __float2bfloat16(p - __bfloat162float(h));
    }
}

// ---------------------------------------------------------------------------
extern "C" void kernel_launch(void* const* d_in, const int* in_sizes, int n_in,
                              void* d_out, int out_size)
{
    int xi = 0;
    for (int i = 0; i < n_in; i++)
        if (in_sizes[i] == BB * TT * CC) { xi = i; break; }
    const float* x = (const float*)d_in[xi];
    const float* w[3];
    int wi = 0;
    for (int i = 0; i < n_in && wi < 3; i++)
        if (i != xi) w[wi++] = (const float*)d_in[i];
    const float* Wk = w[0];
    const float* Wq = w[1];
    const float* Wv = w[2];
    float* out = (float*)d_out;

    bf16 *xhi, *xlo, *Wthi, *Wtlo, *Qhi, *Qlo, *Khi, *Klo, *Vthi, *Vtlo, *Phi, *Plo;
    float *Vf, *S;
    cudaGetSymbolAddress((void**)&xhi, g_xhi);
    cudaGetSymbolAddress((void**)&xlo, g_xlo);
    cudaGetSymbolAddress((void**)&Wthi, g_Wthi);
    cudaGetSymbolAddress((void**)&Wtlo, g_Wtlo);
    cudaGetSymbolAddress((void**)&Qhi, g_Qhi);
    cudaGetSymbolAddress((void**)&Qlo, g_Qlo);
    cudaGetSymbolAddress((void**)&Khi, g_Khi);
    cudaGetSymbolAddress((void**)&Klo, g_Klo);
    cudaGetSymbolAddress((void**)&Vf,  g_Vf);
    cudaGetSymbolAddress((void**)&Vthi, g_Vthi);
    cudaGetSymbolAddress((void**)&Vtlo, g_Vtlo);
    cudaGetSymbolAddress((void**)&S,   g_S);
    cudaGetSymbolAddress((void**)&Phi, g_Phi);
    cudaGetSymbolAddress((void**)&Plo, g_Plo);

    cudaFuncSetAttribute(mma_gemm<0>, cudaFuncAttributeMaxDynamicSharedMemorySize, SMEMSZ);
    cudaFuncSetAttribute(mma_gemm<1>, cudaFuncAttributeMaxDynamicSharedMemorySize, SMEMSZ);
    cudaFuncSetAttribute(mma_gemm<2>, cudaFuncAttributeMaxDynamicSharedMemorySize, SMEMSZ);

    const float scale = 1.0f / 32.0f;
    const size_t WSZ = (size_t)CC * HH;

    split_f32<<<(BB * TT * CC / 4 + 255) / 256, 256>>>(x, xhi, xlo, BB * TT * CC / 4);

    dim3 tb(32, 8);
    transpose_split<<<dim3(HH / 32, CC / 32, 1), tb>>>(Wk, Wthi + 0 * WSZ, Wtlo + 0 * WSZ, CC, HH);
    transpose_split<<<dim3(HH / 32, CC / 32, 1), tb>>>(Wq, Wthi + 1 * WSZ, Wtlo + 1 * WSZ, CC, HH);
    transpose_split<<<dim3(HH / 32, CC / 32, 1), tb>>>(Wv, Wthi + 2 * WSZ, Wtlo + 2 * WSZ, CC, HH);

    // projections: [8192,1024] x [1024,1024]
    dim3 gp(HH / 128, BB * TT / 128, 1);
    mma_gemm<0><<<gp, 256, SMEMSZ>>>(xhi, xlo, 0, Wthi + 1 * WSZ, Wtlo + 1 * WSZ, 0,
                                     CC, nullptr, Qhi, Qlo, 0, HH, 1.f);
    mma_gemm<0><<<gp, 256, SMEMSZ>>>(xhi, xlo, 0, Wthi + 0 * WSZ, Wtlo + 0 * WSZ, 0,
                                     CC, nullptr, Khi, Klo, 0, HH, 1.f);
    mma_gemm<0><<<gp, 256, SMEMSZ>>>(xhi, xlo, 0, Wthi + 2 * WSZ, Wtlo + 2 * WSZ, 0,
                                     CC, Vf, nullptr, nullptr, 0, HH, 1.f);

    // V [b,T,H] -> Vt [b,H,T] bf16 hi/lo
    transpose_split<<<dim3(HH / 32, TT / 32, BB), tb>>>(Vf, Vthi, Vtlo, TT, HH);

    // S = scale * Q K^T, causal tile skip
    dim3 gs(TT / 128, TT / 128, BB);
    mma_gemm<1><<<gs, 256, SMEMSZ>>>(Qhi, Qlo, (size_t)TT * HH, Khi, Klo, (size_t)TT * HH,
                                     HH, S, nullptr, nullptr, (size_t)TT * TT, TT, scale);

    // softmax -> P hi/lo
    softmax_split<<<dim3(TT, BB), 256>>>(S, Phi, Plo);

    // O = P V, causal k-limit
    dim3 gpv(HH / 128, TT / 128, BB);
    mma_gemm<2><<<gpv, 256, SMEMSZ>>>(Phi, Plo, (size_t)TT * TT, Vthi, Vtlo, (size_t)HH * TT,
                                      TT, out, nullptr, nullptr, (size_t)TT * HH, HH, 1.f);
}

// round 4
// speedup vs baseline: 2.7461x; 1.1676x over previous
#include <cuda_runtime.h>
#include <cuda_bf16.h>
#include <cstdint>
#include <math_constants.h>

#define BB 4
#define TT 2048
#define CC 1024
#define HH 1024

typedef __nv_bfloat16 bf16;

// ---------------- scratch (static device globals) ---------------------------
__device__ __align__(16) bf16  g_xhi[(size_t)BB*TT*CC];
__device__ __align__(16) bf16  g_xlo[(size_t)BB*TT*CC];
__device__ __align__(16) bf16  g_Wthi[(size_t)3*CC*HH];   // [Wq^T;Wk^T;Wv^T] rows=3072
__device__ __align__(16) bf16  g_Wtlo[(size_t)3*CC*HH];
__device__ __align__(16) bf16  g_Qhi[(size_t)BB*TT*HH], g_Qlo[(size_t)BB*TT*HH];
__device__ __align__(16) bf16  g_Khi[(size_t)BB*TT*HH], g_Klo[(size_t)BB*TT*HH];
__device__ __align__(16) float g_Vf [(size_t)BB*TT*HH];
__device__ __align__(16) bf16  g_Vthi[(size_t)BB*HH*TT], g_Vtlo[(size_t)BB*HH*TT];
__device__ __align__(16) float g_S  [(size_t)BB*TT*TT];
__device__ __align__(16) bf16  g_Phi[(size_t)BB*TT*TT], g_Plo[(size_t)BB*TT*TT];

// ---------------- PTX helpers ----------------------------------------------
__device__ __forceinline__ uint32_t smem_u32(const void* p) {
    uint32_t a;
    asm("{ .reg .u64 t; cvta.to.shared.u64 t, %1; cvt.u32.u64 %0, t; }"
        : "=r"(a) : "l"(p));
    return a;
}
__device__ __forceinline__ void ldsm4(uint32_t* r, uint32_t addr) {
    asm volatile("ldmatrix.sync.aligned.m8n8.x4.shared.b16 {%0,%1,%2,%3}, [%4];"
                 : "=r"(r[0]), "=r"(r[1]), "=r"(r[2]), "=r"(r[3]) : "r"(addr));
}
__device__ __forceinline__ void mma16816(float* c, const uint32_t* a, const uint32_t* b) {
    asm volatile(
        "mma.sync.aligned.m16n8k16.row.col.f32.bf16.bf16.f32 "
        "{%0,%1,%2,%3}, {%4,%5,%6,%7}, {%8,%9}, {%0,%1,%2,%3};"
        : "+f"(c[0]), "+f"(c[1]), "+f"(c[2]), "+f"(c[3])
        : "r"(a[0]), "r"(a[1]), "r"(a[2]), "r"(a[3]), "r"(b[0]), "r"(b[1]));
}
__device__ __forceinline__ void cpasync16(uint32_t saddr, const void* g) {
    asm volatile("cp.async.cg.shared.global [%0], [%1], 16;" :: "r"(saddr), "l"(g));
}
#define CP_COMMIT()  asm volatile("cp.async.commit_group;" ::: "memory")
#define CP_WAIT1()   asm volatile("cp.async.wait_group 1;" ::: "memory")

// ---------------- bf16x3 tensor-core GEMM ----------------------------------
// 128x128 tile, BK=32, 3-stage cp.async pipeline, 512 threads (warp grid 4x4,
// 32x32 per warp). D = A @ B^T (both K-major).
// MODE 0: projections, B rows 0..3071 = [Wq;Wk;Wv]^T, tri-output epilogue.
// MODE 1: QK^T, triangular-packed grid, scale, fp32 out.
// MODE 2: PV, k-limit (by+1)*128, long rows first, fp32 out.
#define TILE_B   10240          // 128 rows * 80 bytes
#define STAGE_B  40960
#define SMEMSZ   122880         // 3 stages

template<int MODE>
__global__ void __launch_bounds__(512) mma_gemm(
    const bf16* __restrict__ Ah, const bf16* __restrict__ Al,
    const bf16* __restrict__ Bh, const bf16* __restrict__ Bl,
    int K, size_t aB, size_t bB,
    float* __restrict__ Cf, size_t cB, int ldc, float scale,
    bf16* __restrict__ Qhi, bf16* __restrict__ Qlo,
    bf16* __restrict__ Khi, bf16* __restrict__ Klo, float* __restrict__ Vf)
{
    extern __shared__ char smem[];
    int bx, by;
    const int bz = blockIdx.z;
    if (MODE == 1) {
        const int i = blockIdx.x;
        by = (int)((-1.0f + sqrtf(1.0f + 8.0f * (float)i)) * 0.5f);
        while ((by + 1) * (by + 2) / 2 <= i) ++by;
        while (by * (by + 1) / 2 > i) --by;
        bx = i - by * (by + 1) / 2;
    } else if (MODE == 2) {
        bx = blockIdx.x;
        by = gridDim.y - 1 - blockIdx.y;   // long rows first
    } else {
        bx = blockIdx.x;
        by = blockIdx.y;
    }
    int kmax = K;
    if (MODE == 2) { int kl = (by + 1) * 128; kmax = kl < K ? kl : K; }
    const int NC = kmax / 32;

    const int tid  = threadIdx.x;
    const int lane = tid & 31;
    const int warp = tid >> 5;
    const int wm   = warp & 3;     // 4 warps in M -> 32 rows
    const int wn   = warp >> 2;    // 4 warps in N -> 32 cols
    const uint32_t sb = smem_u32(smem);

    const bf16* srcs[4];
    srcs[0] = Ah + bz * aB + (size_t)by * 128 * K;
    srcs[1] = Al + bz * aB + (size_t)by * 128 * K;
    srcs[2] = Bh + bz * bB + (size_t)bx * 128 * K;
    srcs[3] = Bl + bz * bB + (size_t)bx * 128 * K;

    const int lrow = tid >> 2, lcol = tid & 3;   // 512 threads: 1 op per tile
    auto issue = [&](int c) {
        const int k0 = c * 32;
        const uint32_t base = sb + (c % 3) * STAGE_B;
        #pragma unroll
        for (int t4 = 0; t4 < 4; t4++)
            cpasync16(base + t4 * TILE_B + lrow * 80 + lcol * 16,
                      srcs[t4] + k0 + (size_t)lrow * K + lcol * 8);
    };

    float acc[2][4][4] = {};

    issue(0); CP_COMMIT();
    issue(1); CP_COMMIT();

    for (int c = 0; c < NC; c++) {
        CP_WAIT1();
        __syncthreads();
        if (c + 2 < NC) issue(c + 2);
        CP_COMMIT();

        const uint32_t base = sb + (c % 3) * STAGE_B;
        const uint32_t tAh = base, tAl = base + TILE_B;
        const uint32_t tBh = base + 2 * TILE_B, tBl = base + 3 * TILE_B;

        #pragma unroll
        for (int k16 = 0; k16 < 2; k16++) {
            uint32_t ah[2][4], al[2][4], bh[2][4], bl[2][4];
            const int ar   = lane & 15;
            const int aoff = (k16 * 16 + (lane >> 4) * 8) * 2;
            #pragma unroll
            for (int mt = 0; mt < 2; mt++) {
                const uint32_t row = wm * 32 + mt * 16 + ar;
                ldsm4(ah[mt], tAh + row * 80 + aoff);
                ldsm4(al[mt], tAl + row * 80 + aoff);
            }
            const int br   = (lane & 7) + ((lane >> 4) << 3);
            const int boff = (k16 * 16 + ((lane >> 3) & 1) * 8) * 2;
            #pragma unroll
            for (int np = 0; np < 2; np++) {
                const uint32_t row = wn * 32 + np * 16 + br;
                ldsm4(bh[np], tBh + row * 80 + boff);
                ldsm4(bl[np], tBl + row * 80 + boff);
            }
            #pragma unroll
            for (int mt = 0; mt < 2; mt++)
                #pragma unroll
                for (int nt = 0; nt < 4; nt++) {
                    const uint32_t* bhp = &bh[nt >> 1][(nt & 1) * 2];
                    const uint32_t* blp = &bl[nt >> 1][(nt & 1) * 2];
                    mma16816(acc[mt][nt], ah[mt], bhp);
                    mma16816(acc[mt][nt], ah[mt], blp);
                    mma16816(acc[mt][nt], al[mt], bhp);
                }
        }
    }

    // ---------------- epilogue ----------------------------------------------
    const int m0  = by * 128 + wm * 32;
    const int n0g = bx * 128 + wn * 32;

    #pragma unroll
    for (int mt = 0; mt < 2; mt++)
        #pragma unroll
        for (int nt = 0; nt < 4; nt++) {
            const int r  = m0 + mt * 16 + (lane >> 2);
            const float v0 = acc[mt][nt][0], v1 = acc[mt][nt][1];
            const float v2 = acc[mt][nt][2], v3 = acc[mt][nt][3];
            if (MODE == 0) {
                const int blk = bx >> 3;             // 0=Q 1=K 2=V
                const int cc  = (n0g & 1023) + nt * 8 + (lane & 3) * 2;
                const size_t o0 = (size_t)r * HH + cc;
                const size_t o1 = (size_t)(r + 8) * HH + cc;
                if (blk == 2) {
                    *(float2*)(Vf + o0) = make_float2(v0, v1);
                    *(float2*)(Vf + o1) = make_float2(v2, v3);
                } else {
                    bf16* hi = blk ? Khi : Qhi;
                    bf16* lo = blk ? Klo : Qlo;
                    __nv_bfloat162 h0 = __floats2bfloat162_rn(v0, v1);
                    __nv_bfloat162 h1 = __floats2bfloat162_rn(v2, v3);
                    *(__nv_bfloat162*)(hi + o0) = h0;
                    *(__nv_bfloat162*)(hi + o1) = h1;
                    *(__nv_bfloat162*)(lo + o0) = __floats2bfloat162_rn(
                        v0 - __bfloat162float(h0.x), v1 - __bfloat162float(h0.y));
                    *(__nv_bfloat162*)(lo + o1) = __floats2bfloat162_rn(
                        v2 - __bfloat162float(h1.x), v3 - __bfloat162float(h1.y));
                }
            } else {
                const int cc = n0g + nt * 8 + (lane & 3) * 2;
                const size_t o0 = bz * cB + (size_t)r * ldc + cc;
                const size_t o1 = bz * cB + (size_t)(r + 8) * ldc + cc;
                *(float2*)(Cf + o0) = make_float2(v0 * scale, v1 * scale);
                *(float2*)(Cf + o1) = make_float2(v2 * scale, v3 * scale);
            }
        }
}

// ---------------- fp32 -> bf16 hi/lo split ----------------------------------
__global__ void __launch_bounds__(256) split_f32(
    const float* __restrict__ in, bf16* __restrict__ hi, bf16* __restrict__ lo, int n4)
{
    int i = blockIdx.x * blockDim.x + threadIdx.x;
    if (i >= n4) return;
    float4 v = ((const float4*)in)[i];
    __nv_bfloat162 h0 = __floats2bfloat162_rn(v.x, v.y);
    __nv_bfloat162 h1 = __floats2bfloat162_rn(v.z, v.w);
    ((__nv_bfloat162*)hi)[2 * i]     = h0;
    ((__nv_bfloat162*)hi)[2 * i + 1] = h1;
    ((__nv_bfloat162*)lo)[2 * i]     = __floats2bfloat162_rn(
        v.x - __bfloat162float(h0.x), v.y - __bfloat162float(h0.y));
    ((__nv_bfloat162*)lo)[2 * i + 1] = __floats2bfloat162_rn(
        v.z - __bfloat162float(h1.x), v.w - __bfloat162float(h1.y));
}

// ---------------- fp32 transpose + bf16 hi/lo split -------------------------
__global__ void transpose_split(const float* __restrict__ in,
                                bf16* __restrict__ ohi, bf16* __restrict__ olo,
                                int rows, int cols)
{
    __shared__ float t[32][33];
    const size_t base = (size_t)blockIdx.z * rows * cols;
    const int c0 = blockIdx.x * 32, r0 = blockIdx.y * 32;
    const int tx = threadIdx.x, ty = threadIdx.y;
    #pragma unroll
    for (int i = 0; i < 4; i++)
        t[ty + 8 * i][tx] = in[base + (size_t)(r0 + ty + 8 * i) * cols + c0 + tx];
    __syncthreads();
    #pragma unroll
    for (int i = 0; i < 4; i++) {
        float v = t[tx][ty + 8 * i];
        size_t o = base + (size_t)(c0 + ty + 8 * i) * rows + r0 + tx;
        bf16 h = __float2bfloat16(v);
        ohi[o] = h;
        olo[o] = __float2bfloat16(v - __bfloat162float(h));
    }
}

// ---------------- causal softmax -> bf16 hi/lo P ----------------------------
__global__ void __launch_bounds__(256) softmax_split(
    const float* __restrict__ S, bf16* __restrict__ Phi, bf16* __restrict__ Plo)
{
    const int t = blockIdx.x;
    const int b = blockIdx.y;
    const size_t rbase = ((size_t)b * TT + t) * TT;
    const float* row = S + rbase;
    const int len = t + 1;
    const int tid = threadIdx.x;
    const int lane = tid & 31;
    const int warp = tid >> 5;

    __shared__ float red[8];

    float v[8];
    float mx = -CUDART_INF_F;
    #pragma unroll
    for (int i = 0; i < 8; i++) {
        int idx = tid + i * 256;
        v[i] = (idx < len) ? row[idx] : -CUDART_INF_F;
        mx = fmaxf(mx, v[i]);
    }
    #pragma unroll
    for (int o = 16; o > 0; o >>= 1)
        mx = fmaxf(mx, __shfl_xor_sync(0xffffffffu, mx, o));
    if (lane == 0) red[warp] = mx;
    __syncthreads();
    float bmx = red[lane & 7];
    #pragma unroll
    for (int o = 4; o > 0; o >>= 1)
        bmx = fmaxf(bmx, __shfl_xor_sync(0xffffffffu, bmx, o));
    bmx = __shfl_sync(0xffffffffu, bmx, 0);

    float sum = 0.f;
    #pragma unroll
    for (int i = 0; i < 8; i++) {
        int idx = tid + i * 256;
        v[i] = (idx < len) ? __expf(v[i] - bmx) : 0.f;
        sum += v[i];
    }
    #pragma unroll
    for (int o = 16; o > 0; o >>= 1)
        sum += __shfl_xor_sync(0xffffffffu, sum, o);
    if (lane == 0) red[warp] = sum;
    __syncthreads();
    float bsum = red[lane & 7];
    #pragma unroll
    for (int o = 4; o > 0; o >>= 1)
        bsum += __shfl_xor_sync(0xffffffffu, bsum, o);
    bsum = __shfl_sync(0xffffffffu, bsum, 0);

    const float inv = 1.0f / bsum;
    #pragma unroll
    for (int i = 0; i < 8; i++) {
        int idx = tid + i * 256;
        float p = v[i] * inv;
        bf16 h = __float2bfloat16(p);
        Phi[rbase + idx] = h;
        Plo[rbase + idx] = __float2bfloat16(p - __bfloat162float(h));
    }
}

// ---------------------------------------------------------------------------
extern "C" void kernel_launch(void* const* d_in, const int* in_sizes, int n_in,
                              void* d_out, int out_size)
{
    int xi = 0;
    for (int i = 0; i < n_in; i++)
        if (in_sizes[i] == BB * TT * CC) { xi = i; break; }
    const float* x = (const float*)d_in[xi];
    const float* w[3];
    int wi = 0;
    for (int i = 0; i < n_in && wi < 3; i++)
        if (i != xi) w[wi++] = (const float*)d_in[i];
    const float* Wk = w[0];
    const float* Wq = w[1];
    const float* Wv = w[2];
    float* out = (float*)d_out;

    bf16 *xhi, *xlo, *Wthi, *Wtlo, *Qhi, *Qlo, *Khi, *Klo, *Vthi, *Vtlo, *Phi, *Plo;
    float *Vf, *S;
    cudaGetSymbolAddress((void**)&xhi, g_xhi);
    cudaGetSymbolAddress((void**)&xlo, g_xlo);
    cudaGetSymbolAddress((void**)&Wthi, g_Wthi);
    cudaGetSymbolAddress((void**)&Wtlo, g_Wtlo);
    cudaGetSymbolAddress((void**)&Qhi, g_Qhi);
    cudaGetSymbolAddress((void**)&Qlo, g_Qlo);
    cudaGetSymbolAddress((void**)&Khi, g_Khi);
    cudaGetSymbolAddress((void**)&Klo, g_Klo);
    cudaGetSymbolAddress((void**)&Vf,  g_Vf);
    cudaGetSymbolAddress((void**)&Vthi, g_Vthi);
    cudaGetSymbolAddress((void**)&Vtlo, g_Vtlo);
    cudaGetSymbolAddress((void**)&S,   g_S);
    cudaGetSymbolAddress((void**)&Phi, g_Phi);
    cudaGetSymbolAddress((void**)&Plo, g_Plo);

    cudaFuncSetAttribute(mma_gemm<0>, cudaFuncAttributeMaxDynamicSharedMemorySize, SMEMSZ);
    cudaFuncSetAttribute(mma_gemm<1>, cudaFuncAttributeMaxDynamicSharedMemorySize, SMEMSZ);
    cudaFuncSetAttribute(mma_gemm<2>, cudaFuncAttributeMaxDynamicSharedMemorySize, SMEMSZ);

    const float scale = 1.0f / 32.0f;
    const size_t WSZ = (size_t)CC * HH;

    split_f32<<<(BB * TT * CC / 4 + 255) / 256, 256>>>(x, xhi, xlo, BB * TT * CC / 4);

    dim3 tb(32, 8);
    // Wt rows: [0,1024)=Wq^T, [1024,2048)=Wk^T, [2048,3072)=Wv^T
    transpose_split<<<dim3(HH / 32, CC / 32, 1), tb>>>(Wq, Wthi + 0 * WSZ, Wtlo + 0 * WSZ, CC, HH);
    transpose_split<<<dim3(HH / 32, CC / 32, 1), tb>>>(Wk, Wthi + 1 * WSZ, Wtlo + 1 * WSZ, CC, HH);
    transpose_split<<<dim3(HH / 32, CC / 32, 1), tb>>>(Wv, Wthi + 2 * WSZ, Wtlo + 2 * WSZ, CC, HH);

    // fused projections: [8192,1024] x [1024,3072]
    dim3 gp(3 * HH / 128, BB * TT / 128, 1);
    mma_gemm<0><<<gp, 512, SMEMSZ>>>(xhi, xlo, Wthi, Wtlo, CC, 0, 0,
                                     nullptr, 0, 0, 1.f, Qhi, Qlo, Khi, Klo, Vf);

    // V [b,T,H] -> Vt [b,H,T] bf16 hi/lo
    transpose_split<<<dim3(HH / 32, TT / 32, BB), tb>>>(Vf, Vthi, Vtlo, TT, HH);

    // S = scale * Q K^T, triangular-packed grid
    const int ntile = TT / 128;
    dim3 gs(ntile * (ntile + 1) / 2, 1, BB);
    mma_gemm<1><<<gs, 512, SMEMSZ>>>(Qhi, Qlo, Khi, Klo, HH,
                                     (size_t)TT * HH, (size_t)TT * HH,
                                     S, (size_t)TT * TT, TT, scale,
                                     nullptr, nullptr, nullptr, nullptr, nullptr);

    softmax_split<<<dim3(TT, BB), 256>>>(S, Phi, Plo);

    // O = P V, causal k-limit, long rows first
    dim3 gpv(HH / 128, TT / 128, BB);
    mma_gemm<2><<<gpv, 512, SMEMSZ>>>(Phi, Plo, Vthi, Vtlo, TT,
                                      (size_t)TT * TT, (size_t)HH * TT,
                                      out, (size_t)TT * HH, HH, 1.f,
                                      nullptr, nullptr, nullptr, nullptr, nullptr);
}

// round 5
// speedup vs baseline: 6.3220x; 2.3022x over previous
#include <cuda_runtime.h>
#include <cuda_fp16.h>
#include <cstdint>
#include <math_constants.h>

#define BB 4
#define TT 2048
#define CC 1024
#define HH 1024

typedef __half fp16;

// ---------------- scratch (static device globals) ---------------------------
__device__ __align__(16) fp16  g_xh [(size_t)BB*TT*CC];
__device__ __align__(16) fp16  g_Wt [(size_t)3*CC*HH];   // [Wq^T;Wk^T;Wv^T] rows=3072
__device__ __align__(16) fp16  g_Qh [(size_t)BB*TT*HH];
__device__ __align__(16) fp16  g_Kh [(size_t)BB*TT*HH];
__device__ __align__(16) float g_Vf [(size_t)BB*TT*HH];
__device__ __align__(16) fp16  g_Vt [(size_t)BB*HH*TT];  // V^T per batch
__device__ __align__(16) float g_S  [(size_t)BB*TT*TT];
__device__ __align__(16) fp16  g_P  [(size_t)BB*TT*TT];

// ---------------- PTX helpers ----------------------------------------------
__device__ __forceinline__ uint32_t smem_u32(const void* p) {
    uint32_t a;
    asm("{ .reg .u64 t; cvta.to.shared.u64 t, %1; cvt.u32.u64 %0, t; }"
        : "=r"(a) : "l"(p));
    return a;
}
__device__ __forceinline__ void ldsm4(uint32_t* r, uint32_t addr) {
    asm volatile("ldmatrix.sync.aligned.m8n8.x4.shared.b16 {%0,%1,%2,%3}, [%4];"
                 : "=r"(r[0]), "=r"(r[1]), "=r"(r[2]), "=r"(r[3]) : "r"(addr));
}
__device__ __forceinline__ void mma16816(float* c, const uint32_t* a, const uint32_t* b) {
    asm volatile(
        "mma.sync.aligned.m16n8k16.row.col.f32.f16.f16.f32 "
        "{%0,%1,%2,%3}, {%4,%5,%6,%7}, {%8,%9}, {%0,%1,%2,%3};"
        : "+f"(c[0]), "+f"(c[1]), "+f"(c[2]), "+f"(c[3])
        : "r"(a[0]), "r"(a[1]), "r"(a[2]), "r"(a[3]), "r"(b[0]), "r"(b[1]));
}
__device__ __forceinline__ void cpasync16(uint32_t saddr, const void* g) {
    asm volatile("cp.async.cg.shared.global [%0], [%1], 16;" :: "r"(saddr), "l"(g));
}
#define CP_COMMIT()  asm volatile("cp.async.commit_group;" ::: "memory")
#define CP_WAIT1()   asm volatile("cp.async.wait_group 1;" ::: "memory")

// ---------------- single-pass fp16 tensor-core GEMM -------------------------
// 128x128 tile, BK=32, 3-stage cp.async pipeline, 256 threads (warp grid 2Mx4N,
// 64x32 per warp). D = A @ B^T, both K-major fp16.
// MODE 0: fused QKV projections (B rows [Wq;Wk;Wv]^T), Q/K fp16 + V fp32 out.
// MODE 1: QK^T, triangular-packed grid, scale, fp32 S out.
// MODE 2: PV, k-limit (by+1)*128, long rows first, fp32 out.
#define TILE_B   10240          // 128 rows * 80 bytes (32 fp16 = 64B + 16 pad)
#define STAGE_B  20480          // 2 tiles (A, B)
#define SMEMSZ   61440          // 3 stages

template<int MODE>
__global__ void __launch_bounds__(256, 2) mma_gemm(
    const fp16* __restrict__ A, const fp16* __restrict__ B,
    int K, size_t aB, size_t bB,
    float* __restrict__ Cf, size_t cB, int ldc, float scale,
    fp16* __restrict__ Qh, fp16* __restrict__ Kh, float* __restrict__ Vf)
{
    extern __shared__ char smem[];
    int bx, by;
    const int bz = blockIdx.z;
    if (MODE == 1) {
        const int i = blockIdx.x;
        by = (int)((-1.0f + sqrtf(1.0f + 8.0f * (float)i)) * 0.5f);
        while ((by + 1) * (by + 2) / 2 <= i) ++by;
        while (by * (by + 1) / 2 > i) --by;
        bx = i - by * (by + 1) / 2;
    } else if (MODE == 2) {
        bx = blockIdx.x;
        by = gridDim.y - 1 - blockIdx.y;   // long rows first
    } else {
        bx = blockIdx.x;
        by = blockIdx.y;
    }
    int kmax = K;
    if (MODE == 2) { int kl = (by + 1) * 128; kmax = kl < K ? kl : K; }
    const int NC = kmax / 32;

    const int tid  = threadIdx.x;
    const int lane = tid & 31;
    const int warp = tid >> 5;
    const int wm   = warp & 1;     // 2 warps in M -> 64 rows
    const int wn   = warp >> 1;    // 4 warps in N -> 32 cols
    const uint32_t sb = smem_u32(smem);

    const fp16* srcA = A + bz * aB + (size_t)by * 128 * K;
    const fp16* srcB = B + bz * bB + (size_t)bx * 128 * K;

    const int lrow = tid >> 1, lcol = tid & 1;  // 256 thr: 2 cp.async per tile
    auto issue = [&](int c) {
        const int k0 = c * 32;
        const uint32_t base = sb + (c % 3) * STAGE_B;
        cpasync16(base + lrow * 80 + lcol * 32,
                  srcA + k0 + (size_t)lrow * K + lcol * 16);
        cpasync16(base + lrow * 80 + lcol * 32 + 16,
                  srcA + k0 + (size_t)lrow * K + lcol * 16 + 8);
        cpasync16(base + TILE_B + lrow * 80 + lcol * 32,
                  srcB + k0 + (size_t)lrow * K + lcol * 16);
        cpasync16(base + TILE_B + lrow * 80 + lcol * 32 + 16,
                  srcB + k0 + (size_t)lrow * K + lcol * 16 + 8);
    };

    float acc[4][4][4] = {};

    issue(0); CP_COMMIT();
    issue(1); CP_COMMIT();

    for (int c = 0; c < NC; c++) {
        CP_WAIT1();
        __syncthreads();
        if (c + 2 < NC) issue(c + 2);
        CP_COMMIT();

        const uint32_t base = sb + (c % 3) * STAGE_B;
        const uint32_t tA = base, tB = base + TILE_B;

        #pragma unroll
        for (int k16 = 0; k16 < 2; k16++) {
            uint32_t af[4][4], bf[2][4];
            const int ar   = lane & 15;
            const int aoff = (k16 * 16 + (lane >> 4) * 8) * 2;
            #pragma unroll
            for (int mt = 0; mt < 4; mt++) {
                const uint32_t row = wm * 64 + mt * 16 + ar;
                ldsm4(af[mt], tA + row * 80 + aoff);
            }
            const int br   = (lane & 7) + ((lane >> 4) << 3);
            const int boff = (k16 * 16 + ((lane >> 3) & 1) * 8) * 2;
            #pragma unroll
            for (int np = 0; np < 2; np++) {
                const uint32_t row = wn * 32 + np * 16 + br;
                ldsm4(bf[np], tB + row * 80 + boff);
            }
            #pragma unroll
            for (int mt = 0; mt < 4; mt++)
                #pragma unroll
                for (int nt = 0; nt < 4; nt++)
                    mma16816(acc[mt][nt], af[mt], &bf[nt >> 1][(nt & 1) * 2]);
        }
    }

    // ---------------- epilogue ----------------------------------------------
    const int m0  = by * 128 + wm * 64;
    const int n0g = bx * 128 + wn * 32;

    #pragma unroll
    for (int mt = 0; mt < 4; mt++)
        #pragma unroll
        for (int nt = 0; nt < 4; nt++) {
            const int r  = m0 + mt * 16 + (lane >> 2);
            const float v0 = acc[mt][nt][0], v1 = acc[mt][nt][1];
            const float v2 = acc[mt][nt][2], v3 = acc[mt][nt][3];
            if (MODE == 0) {
                const int blk = bx >> 3;             // 0=Q 1=K 2=V
                const int cc  = (n0g & 1023) + nt * 8 + (lane & 3) * 2;
                const size_t o0 = (size_t)r * HH + cc;
                const size_t o1 = (size_t)(r + 8) * HH + cc;
                if (blk == 2) {
                    *(float2*)(Vf + o0) = make_float2(v0, v1);
                    *(float2*)(Vf + o1) = make_float2(v2, v3);
                } else {
                    fp16* dst = blk ? Kh : Qh;
                    *(__half2*)(dst + o0) = __floats2half2_rn(v0, v1);
                    *(__half2*)(dst + o1) = __floats2half2_rn(v2, v3);
                }
            } else {
                const int cc = n0g + nt * 8 + (lane & 3) * 2;
                const size_t o0 = bz * cB + (size_t)r * ldc + cc;
                const size_t o1 = bz * cB + (size_t)(r + 8) * ldc + cc;
                *(float2*)(Cf + o0) = make_float2(v0 * scale, v1 * scale);
                *(float2*)(Cf + o1) = make_float2(v2 * scale, v3 * scale);
            }
        }
}

// ---------------- fp32 -> fp16 convert --------------------------------------
__global__ void __launch_bounds__(256) conv_f16(
    const float* __restrict__ in, fp16* __restrict__ out, int n4)
{
    int i = blockIdx.x * blockDim.x + threadIdx.x;
    if (i >= n4) return;
    float4 v = ((const float4*)in)[i];
    ((__half2*)out)[2 * i]     = __floats2half2_rn(v.x, v.y);
    ((__half2*)out)[2 * i + 1] = __floats2half2_rn(v.z, v.w);
}

// ---------------- fp32 transpose -> fp16 ------------------------------------
__global__ void transpose_f16(const float* __restrict__ in, fp16* __restrict__ out,
                              int rows, int cols)
{
    __shared__ float t[32][33];
    const size_t base = (size_t)blockIdx.z * rows * cols;
    const int c0 = blockIdx.x * 32, r0 = blockIdx.y * 32;
    const int tx = threadIdx.x, ty = threadIdx.y;
    #pragma unroll
    for (int i = 0; i < 4; i++)
        t[ty + 8 * i][tx] = in[base + (size_t)(r0 + ty + 8 * i) * cols + c0 + tx];
    __syncthreads();
    #pragma unroll
    for (int i = 0; i < 4; i++)
        out[base + (size_t)(c0 + ty + 8 * i) * rows + r0 + tx] =
            __float2half(t[tx][ty + 8 * i]);
}

// ---------------- causal softmax: fp32 S -> fp16 P --------------------------
__global__ void __launch_bounds__(256) softmax_p(
    const float* __restrict__ S, fp16* __restrict__ P)
{
    const int t = blockIdx.x;
    const int b = blockIdx.y;
    const size_t rbase = ((size_t)b * TT + t) * TT;
    const float* row = S + rbase;
    const int len = t + 1;
    const int tid = threadIdx.x;
    const int lane = tid & 31;
    const int warp = tid >> 5;

    __shared__ float red[8];

    float v[8];
    float mx = -CUDART_INF_F;
    #pragma unroll
    for (int i = 0; i < 8; i++) {
        int idx = tid + i * 256;
        v[i] = (idx < len) ? row[idx] : -CUDART_INF_F;
        mx = fmaxf(mx, v[i]);
    }
    #pragma unroll
    for (int o = 16; o > 0; o >>= 1)
        mx = fmaxf(mx, __shfl_xor_sync(0xffffffffu, mx, o));
    if (lane == 0) red[warp] = mx;
    __syncthreads();
    float bmx = red[lane & 7];
    #pragma unroll
    for (int o = 4; o > 0; o >>= 1)
        bmx = fmaxf(bmx, __shfl_xor_sync(0xffffffffu, bmx, o));
    bmx = __shfl_sync(0xffffffffu, bmx, 0);

    float sum = 0.f;
    #pragma unroll
    for (int i = 0; i < 8; i++) {
        int idx = tid + i * 256;
        v[i] = (idx < len) ? __expf(v[i] - bmx) : 0.f;
        sum += v[i];
    }
    #pragma unroll
    for (int o = 16; o > 0; o >>= 1)
        sum += __shfl_xor_sync(0xffffffffu, sum, o);
    if (lane == 0) red[warp] = sum;
    __syncthreads();
    float bsum = red[lane & 7];
    #pragma unroll
    for (int o = 4; o > 0; o >>= 1)
        bsum += __shfl_xor_sync(0xffffffffu, bsum, o);
    bsum = __shfl_sync(0xffffffffu, bsum, 0);

    const float inv = 1.0f / bsum;
    #pragma unroll
    for (int i = 0; i < 8; i++) {
        int idx = tid + i * 256;
        P[rbase + idx] = __float2half(v[i] * inv);
    }
}

// ---------------------------------------------------------------------------
extern "C" void kernel_launch(void* const* d_in, const int* in_sizes, int n_in,
                              void* d_out, int out_size)
{
    int xi = 0;
    for (int i = 0; i < n_in; i++)
        if (in_sizes[i] == BB * TT * CC) { xi = i; break; }
    const float* x = (const float*)d_in[xi];
    const float* w[3];
    int wi = 0;
    for (int i = 0; i < n_in && wi < 3; i++)
        if (i != xi) w[wi++] = (const float*)d_in[i];
    const float* Wk = w[0];
    const float* Wq = w[1];
    const float* Wv = w[2];
    float* out = (float*)d_out;

    fp16 *xh, *Wt, *Qh, *Kh, *Vt, *P;
    float *Vf, *S;
    cudaGetSymbolAddress((void**)&xh, g_xh);
    cudaGetSymbolAddress((void**)&Wt, g_Wt);
    cudaGetSymbolAddress((void**)&Qh, g_Qh);
    cudaGetSymbolAddress((void**)&Kh, g_Kh);
    cudaGetSymbolAddress((void**)&Vf, g_Vf);
    cudaGetSymbolAddress((void**)&Vt, g_Vt);
    cudaGetSymbolAddress((void**)&S,  g_S);
    cudaGetSymbolAddress((void**)&P,  g_P);

    cudaFuncSetAttribute(mma_gemm<0>, cudaFuncAttributeMaxDynamicSharedMemorySize, SMEMSZ);
    cudaFuncSetAttribute(mma_gemm<1>, cudaFuncAttributeMaxDynamicSharedMemorySize, SMEMSZ);
    cudaFuncSetAttribute(mma_gemm<2>, cudaFuncAttributeMaxDynamicSharedMemorySize, SMEMSZ);

    const float scale = 1.0f / 32.0f;
    const size_t WSZ = (size_t)CC * HH;

    conv_f16<<<(BB * TT * CC / 4 + 255) / 256, 256>>>(x, xh, BB * TT * CC / 4);

    dim3 tb(32, 8);
    // Wt rows: [0,1024)=Wq^T, [1024,2048)=Wk^T, [2048,3072)=Wv^T
    transpose_f16<<<dim3(HH / 32, CC / 32, 1), tb>>>(Wq, Wt + 0 * WSZ, CC, HH);
    transpose_f16<<<dim3(HH / 32, CC / 32, 1), tb>>>(Wk, Wt + 1 * WSZ, CC, HH);
    transpose_f16<<<dim3(HH / 32, CC / 32, 1), tb>>>(Wv, Wt + 2 * WSZ, CC, HH);

    // fused projections: [8192,1024] x [1024,3072]
    dim3 gp(3 * HH / 128, BB * TT / 128, 1);
    mma_gemm<0><<<gp, 256, SMEMSZ>>>(xh, Wt, CC, 0, 0,
                                     nullptr, 0, 0, 1.f, Qh, Kh, Vf);

    // V [b,T,H] -> Vt [b,H,T] fp16
    transpose_f16<<<dim3(HH / 32, TT / 32, BB), tb>>>(Vf, Vt, TT, HH);

    // S = scale * Q K^T, triangular-packed grid
    const int ntile = TT / 128;
    dim3 gs(ntile * (ntile + 1) / 2, 1, BB);
    mma_gemm<1><<<gs, 256, SMEMSZ>>>(Qh, Kh, HH,
                                     (size_t)TT * HH, (size_t)TT * HH,
                                     S, (size_t)TT * TT, TT, scale,
                                     nullptr, nullptr, nullptr);

    softmax_p<<<dim3(TT, BB), 256>>>(S, P);

    // O = P V, causal k-limit, long rows first
    dim3 gpv(HH / 128, TT / 128, BB);
    mma_gemm<2><<<gpv, 256, SMEMSZ>>>(P, Vt, TT,
                                      (size_t)TT * TT, (size_t)HH * TT,
                                      out, (size_t)TT * HH, HH, 1.f,
                                      nullptr, nullptr, nullptr);
}